// round 7
// baseline (speedup 1.0000x reference)
#include <cuda_runtime.h>
#include <math.h>
#include <stdint.h>

// ---------------- problem constants ----------------
#define BATCH   32
#define DMODEL  768
#define NHEAD   12
#define HDIM    64
#define NLAYER  12
#define MLPD    3072
#define SEQ1    197
#define SEQ2    222
#define NPATCH_ 196
#define POOLN   10
#define SELN    5
#define PLENN   5
#define NCLSN   100
#define MAXTOK  (BATCH*SEQ2)   // 7104

// ---------------- scratch (device globals; no allocs allowed) ----------------
__device__ float g_x   [MAXTOK*DMODEL];
__device__ float g_h   [MAXTOK*DMODEL];
__device__ float g_qkv [MAXTOK*3*DMODEL];
__device__ float g_ao  [MAXTOK*DMODEL];
__device__ float g_mlp [MAXTOK*MLPD];
__device__ float g_att [(size_t)BATCH*NHEAD*SEQ2*SEQ2];
__device__ float g_xe  [BATCH*SEQ1*DMODEL];
__device__ float g_qcls[BATCH*DMODEL];
__device__ float g_quad[BATCH*POOLN];
__device__ float g_lognorm[POOLN];
__device__ int   g_topk[BATCH*SELN];
__device__ float g_feat[BATCH*DMODEL];

// ---------------- block reduce (full warp 0 executes stage 2: legal) ----------------
__device__ __forceinline__ float block_reduce_sum(float v, float* sh) {
    int t = threadIdx.x, lane = t & 31, w = t >> 5;
    #pragma unroll
    for (int o = 16; o; o >>= 1) v += __shfl_down_sync(0xffffffffu, v, o);
    if (lane == 0) sh[w] = v;
    __syncthreads();
    if (w == 0) {
        float r = (t < ((int)blockDim.x >> 5)) ? sh[t] : 0.f;
        #pragma unroll
        for (int o = 4; o; o >>= 1) r += __shfl_down_sync(0xffffffffu, r, o);
        if (lane == 0) sh[0] = r;
    }
    __syncthreads();
    float out = sh[0];
    __syncthreads();
    return out;
}

// ---------------- SGEMM: C[M,N] = A[M,K] @ B[K,N] + bias (+gelu | +res) ----------------
// OPT: 0 = bias only, 1 = bias+exact GELU, 2 = bias+residual
// Requires: K % 8 == 0, N % 128 == 0. M arbitrary (clamped loads, guarded stores).
// BM=BN=128, BK=8, 256 threads, 8x8 micro-tile, double-buffered smem.
template<int OPT>
__global__ void __launch_bounds__(256, 2) gemm_k(
    const float* __restrict__ A, const float* __restrict__ Bw,
    const float* __restrict__ bias, const float* __restrict__ res,
    float* __restrict__ C, int M, int N, int K)
{
    const int BK = 8;
    __shared__ float As[2][BK][132];   // [k][m], padded -> conflict-free transpose
    __shared__ float Bs[2][BK][128];   // [k][n]

    int t  = threadIdx.x;
    int bm = blockIdx.y * 128, bn = blockIdx.x * 128;

    // global-load mapping
    int arow = t >> 1;           // 0..127
    int acol = (t & 1) << 2;     // 0 or 4
    int brow = t >> 5;           // 0..7
    int bcol = (t & 31) << 2;    // 0..124
    int ga_row = bm + arow; if (ga_row > M - 1) ga_row = M - 1;  // clamp (valid mem)
    const float* Aptr = A  + (size_t)ga_row * K + acol;
    const float* Bptr = Bw + (size_t)brow * N + bn + bcol;

    // compute mapping
    int tm = t >> 4, tn = t & 15;        // 16x16 thread grid

    float acc[8][8];
    #pragma unroll
    for (int i = 0; i < 8; i++)
        #pragma unroll
        for (int j = 0; j < 8; j++) acc[i][j] = 0.f;

    // preload tile 0
    float4 ra = *(const float4*)(Aptr);
    float4 rb = *(const float4*)(Bptr);
    As[0][acol+0][arow] = ra.x; As[0][acol+1][arow] = ra.y;
    As[0][acol+2][arow] = ra.z; As[0][acol+3][arow] = ra.w;
    *(float4*)&Bs[0][brow][bcol] = rb;
    __syncthreads();

    int cur = 0;
    for (int k0 = BK; k0 < K; k0 += BK) {
        // prefetch next tile into registers
        ra = *(const float4*)(Aptr + k0);
        rb = *(const float4*)(Bptr + (size_t)k0 * N);

        // compute current tile
        #pragma unroll
        for (int kk = 0; kk < BK; kk++) {
            float4 a0 = *(const float4*)&As[cur][kk][tm*4];
            float4 a1 = *(const float4*)&As[cur][kk][tm*4 + 64];
            float4 b0 = *(const float4*)&Bs[cur][kk][tn*4];
            float4 b1 = *(const float4*)&Bs[cur][kk][tn*4 + 64];
            float av[8] = {a0.x,a0.y,a0.z,a0.w,a1.x,a1.y,a1.z,a1.w};
            float bv[8] = {b0.x,b0.y,b0.z,b0.w,b1.x,b1.y,b1.z,b1.w};
            #pragma unroll
            for (int i = 0; i < 8; i++)
                #pragma unroll
                for (int j = 0; j < 8; j++) acc[i][j] += av[i] * bv[j];
        }

        int nxt = cur ^ 1;
        As[nxt][acol+0][arow] = ra.x; As[nxt][acol+1][arow] = ra.y;
        As[nxt][acol+2][arow] = ra.z; As[nxt][acol+3][arow] = ra.w;
        *(float4*)&Bs[nxt][brow][bcol] = rb;
        __syncthreads();
        cur = nxt;
    }
    // last tile
    #pragma unroll
    for (int kk = 0; kk < BK; kk++) {
        float4 a0 = *(const float4*)&As[cur][kk][tm*4];
        float4 a1 = *(const float4*)&As[cur][kk][tm*4 + 64];
        float4 b0 = *(const float4*)&Bs[cur][kk][tn*4];
        float4 b1 = *(const float4*)&Bs[cur][kk][tn*4 + 64];
        float av[8] = {a0.x,a0.y,a0.z,a0.w,a1.x,a1.y,a1.z,a1.w};
        float bv[8] = {b0.x,b0.y,b0.z,b0.w,b1.x,b1.y,b1.z,b1.w};
        #pragma unroll
        for (int i = 0; i < 8; i++)
            #pragma unroll
            for (int j = 0; j < 8; j++) acc[i][j] += av[i] * bv[j];
    }

    // epilogue
    int gn0 = bn + tn*4, gn1 = bn + tn*4 + 64;
    float4 bias0 = *(const float4*)(bias + gn0);
    float4 bias1 = *(const float4*)(bias + gn1);
    #pragma unroll
    for (int i = 0; i < 8; i++) {
        int gm = bm + (i < 4 ? tm*4 + i : 64 + tm*4 + (i - 4));
        if (gm >= M) continue;
        float v[8];
        v[0] = acc[i][0] + bias0.x; v[1] = acc[i][1] + bias0.y;
        v[2] = acc[i][2] + bias0.z; v[3] = acc[i][3] + bias0.w;
        v[4] = acc[i][4] + bias1.x; v[5] = acc[i][5] + bias1.y;
        v[6] = acc[i][6] + bias1.z; v[7] = acc[i][7] + bias1.w;
        if (OPT == 1) {
            #pragma unroll
            for (int j = 0; j < 8; j++)
                v[j] = 0.5f * v[j] * (1.0f + erff(v[j] * 0.70710678118654752f));
        }
        if (OPT == 2) {
            float4 r0 = *(const float4*)(res + (size_t)gm * N + gn0);
            float4 r1 = *(const float4*)(res + (size_t)gm * N + gn1);
            v[0] += r0.x; v[1] += r0.y; v[2] += r0.z; v[3] += r0.w;
            v[4] += r1.x; v[5] += r1.y; v[6] += r1.z; v[7] += r1.w;
        }
        float4 o0 = {v[0], v[1], v[2], v[3]};
        float4 o1 = {v[4], v[5], v[6], v[7]};
        *(float4*)(C + (size_t)gm * N + gn0) = o0;
        *(float4*)(C + (size_t)gm * N + gn1) = o1;
    }
}

// ---------------- LayerNorm (row = 768) ----------------
__global__ void layernorm_k(const float* __restrict__ X, float* __restrict__ Y,
                            const float* __restrict__ w, const float* __restrict__ bs,
                            size_t in_rstride, size_t out_rstride)
{
    __shared__ float sh[32];
    const float* x = X + (size_t)blockIdx.x * in_rstride;
    float* y = Y + (size_t)blockIdx.x * out_rstride;
    int t = threadIdx.x;
    float a = x[t], b = x[t+256], c = x[t+512];
    float s = block_reduce_sum(a + b + c, sh);
    float mean = s * (1.f / 768.f);
    float d0 = a - mean, d1 = b - mean, d2 = c - mean;
    float sq = block_reduce_sum(d0*d0 + d1*d1 + d2*d2, sh);
    float rstd = rsqrtf(sq * (1.f / 768.f) + 1e-6f);
    y[t]     = d0 * rstd * w[t]     + bs[t];
    y[t+256] = d1 * rstd * w[t+256] + bs[t+256];
    y[t+512] = d2 * rstd * w[t+512] + bs[t+512];
}

// ---------------- patchify ----------------
__global__ void patchify_k(const float* __restrict__ in, float* __restrict__ out) {
    int idx = blockIdx.x * 256 + threadIdx.x;
    if (idx >= BATCH * NPATCH_ * DMODEL) return;
    int d = idx % DMODEL;
    int pr = (idx / DMODEL) % NPATCH_;
    int b = idx / (DMODEL * NPATCH_);
    int c = d >> 8, rem = d & 255, ph = rem >> 4, pw = rem & 15;
    int gy = pr / 14, gx = pr % 14;
    out[idx] = in[(((size_t)b*3 + c)*224 + gy*16 + ph)*224 + gx*16 + pw];
}

// ---------------- embed: cls + pos, write both g_xe and g_x ----------------
__global__ void embed_k(const float* __restrict__ pe, const float* __restrict__ cls,
                        const float* __restrict__ pos, float* __restrict__ xe, float* __restrict__ x)
{
    int idx = blockIdx.x * 256 + threadIdx.x;
    if (idx >= BATCH * SEQ1 * DMODEL) return;
    int d = idx % DMODEL;
    int r = (idx / DMODEL) % SEQ1;
    int b = idx / (DMODEL * SEQ1);
    float v = (r == 0) ? cls[d] : pe[((size_t)b*NPATCH_ + r - 1)*DMODEL + d];
    v += pos[(size_t)r*DMODEL + d];
    xe[idx] = v; x[idx] = v;
}

// ---------------- attention ----------------
__global__ void attn_scores_k(const float* __restrict__ qkv, float* __restrict__ att, int S) {
    int bh = blockIdx.z;
    int b = bh / NHEAD, h = bh % NHEAD;
    int q0 = blockIdx.y * 32, k0 = blockIdx.x * 32;
    __shared__ float Qs[32][65], Ks[32][65];
    int t = threadIdx.x;
    #pragma unroll
    for (int e = 0; e < 8; e++) {
        int idx = e * 256 + t;
        int r = idx >> 6, c = idx & 63;
        int qs = q0 + r, ks = k0 + r;
        Qs[r][c] = (qs < S) ? qkv[(size_t)(b*S + qs)*2304 + h*64 + c] : 0.f;
        Ks[r][c] = (ks < S) ? qkv[(size_t)(b*S + ks)*2304 + 768 + h*64 + c] : 0.f;
    }
    __syncthreads();
    int kc = t & 31, qb = (t >> 5) * 4;
    float acc[4] = {0.f, 0.f, 0.f, 0.f};
    #pragma unroll 8
    for (int hd = 0; hd < 64; hd++) {
        float kv = Ks[kc][hd];
        #pragma unroll
        for (int i = 0; i < 4; i++) acc[i] += Qs[qb+i][hd] * kv;
    }
    #pragma unroll
    for (int i = 0; i < 4; i++) {
        int qq = q0 + qb + i;
        if (qq < S && k0 + kc < S)
            att[((size_t)bh*S + qq)*S + k0 + kc] = acc[i] * 0.125f;
    }
}

__global__ void softmax_k(float* __restrict__ att, int S) {
    __shared__ float sh[32];
    size_t row = blockIdx.x;
    float* p = att + row * S;
    int t = threadIdx.x;
    float v = (t < S) ? p[t] : -1e30f;
    float m = v;
    #pragma unroll
    for (int o = 16; o; o >>= 1) m = fmaxf(m, __shfl_down_sync(0xffffffffu, m, o));
    if ((t & 31) == 0) sh[t >> 5] = m;
    __syncthreads();
    // stage 2: FULL warp 0 executes the shfl (fixes partial-warp/full-mask deadlock)
    if (t < 32) {
        float r = (t < 8) ? sh[t] : -1e30f;
        #pragma unroll
        for (int o = 4; o; o >>= 1) r = fmaxf(r, __shfl_down_sync(0xffffffffu, r, o));
        if (t == 0) sh[0] = r;
    }
    __syncthreads();
    m = sh[0];
    __syncthreads();
    float e = (t < S) ? __expf(v - m) : 0.f;
    float s = block_reduce_sum(e, sh);
    if (t < S) p[t] = e / s;
}

__global__ void attn_av_k(const float* __restrict__ qkv, const float* __restrict__ att,
                          float* __restrict__ out, int S)
{
    int bh = blockIdx.y;
    int b = bh / NHEAD, h = bh % NHEAD;
    int s0 = blockIdx.x * 32;
    __shared__ float Ats[32][33];
    __shared__ float Vs[32][65];
    int t = threadIdx.x;
    int hd = t & 63, sg = t >> 6;
    float acc[8];
    #pragma unroll
    for (int i = 0; i < 8; i++) acc[i] = 0.f;
    int nk = (S + 31) / 32;
    for (int kt = 0; kt < nk; kt++) {
        int k0 = kt * 32;
        #pragma unroll
        for (int e = 0; e < 4; e++) {
            int idx = e * 256 + t;
            int r = idx >> 5, c = idx & 31;
            Ats[r][c] = (s0 + r < S && k0 + c < S) ? att[((size_t)bh*S + s0 + r)*S + k0 + c] : 0.f;
        }
        #pragma unroll
        for (int e = 0; e < 8; e++) {
            int idx = e * 256 + t;
            int r = idx >> 6, c = idx & 63;
            Vs[r][c] = (k0 + r < S) ? qkv[(size_t)(b*S + k0 + r)*2304 + 1536 + h*64 + c] : 0.f;
        }
        __syncthreads();
        #pragma unroll 8
        for (int kk = 0; kk < 32; kk++) {
            float vv = Vs[kk][hd];
            #pragma unroll
            for (int i = 0; i < 8; i++) acc[i] += Ats[sg*8 + i][kk] * vv;
        }
        __syncthreads();
    }
    #pragma unroll
    for (int i = 0; i < 8; i++) {
        int s = s0 + sg*8 + i;
        if (s < S) out[(size_t)(b*S + s)*DMODEL + h*64 + hd] = acc[i];
    }
}

// ---------------- routing ----------------
__global__ void quad_k(const float* __restrict__ qcls, const float* __restrict__ keys,
                       const float* __restrict__ invvar, float* __restrict__ quad)
{
    int b = blockIdx.x / POOLN, p = blockIdx.x % POOLN;
    __shared__ float diff[DMODEL];
    __shared__ float wacc[8];
    int t = threadIdx.x;
    for (int i = t; i < DMODEL; i += 256)
        diff[i] = qcls[(size_t)b*DMODEL + i] - keys[(size_t)p*DMODEL + i];
    __syncthreads();
    int w = t >> 5, lane = t & 31;
    const float* iv = invvar + (size_t)p * DMODEL * DMODEL;
    float acc = 0.f;
    for (int d = w; d < DMODEL; d += 8) {
        float s = 0.f;
        for (int e = lane; e < DMODEL; e += 32) s += iv[(size_t)d*DMODEL + e] * diff[e];
        #pragma unroll
        for (int o = 16; o; o >>= 1) s += __shfl_down_sync(0xffffffffu, s, o);
        if (lane == 0) acc += diff[d] * s;
    }
    if (lane == 0) wacc[w] = acc;
    __syncthreads();
    if (t == 0) {
        float q = 0.f;
        #pragma unroll
        for (int i = 0; i < 8; i++) q += wacc[i];
        quad[b*POOLN + p] = q;
    }
}

__global__ void lognorm_k(const float* __restrict__ var, float* __restrict__ out) {
    __shared__ float sh[32];
    int p = blockIdx.x, t = threadIdx.x;
    const float* vp = var + (size_t)p * DMODEL * DMODEL;
    float s = 0.f;
    for (int i = t; i < DMODEL*DMODEL; i += 256) { float v = vp[i]; s += v*v; }
    float tot = block_reduce_sum(s, sh);
    if (t == 0) out[p] = 0.25f * logf(tot);   // 0.5*log(sqrt(sumsq))
}

__global__ void topk_k(const float* __restrict__ quad, const float* __restrict__ lognorm,
                       const float* __restrict__ freq, int* __restrict__ topk)
{
    __shared__ float lwn[POOLN];
    int t = threadIdx.x;
    if (t == 0) {
        float mx = -1e30f;
        for (int p = 0; p < POOLN; p++) mx = fmaxf(mx, freq[p]);
        float w[POOLN]; float nrm = 0.f;
        for (int p = 0; p < POOLN; p++) { w[p] = mx - freq[p]; nrm += w[p]*w[p]; }
        nrm = fmaxf(sqrtf(nrm), 1e-12f);
        for (int p = 0; p < POOLN; p++) lwn[p] = logf(fmaxf(w[p]/nrm, 1e-30f));
    }
    __syncthreads();
    if (t < BATCH) {
        float sc[POOLN];
        bool used[POOLN];
        for (int p = 0; p < POOLN; p++) {
            sc[p] = -0.5f * quad[t*POOLN + p] + lognorm[p] + lwn[p];
            used[p] = false;
        }
        for (int j = 0; j < SELN; j++) {
            int best = -1; float bv = 1e38f;
            for (int p = 0; p < POOLN; p++)
                if (!used[p] && sc[p] < bv) { bv = sc[p]; best = p; }
            if (best < 0) best = 0;   // NaN safety: never index OOB
            used[best] = true;
            topk[t*SELN + j] = best;
        }
    }
}

__global__ void buildsx_k(const float* __restrict__ xe, const float* __restrict__ prompts,
                          const float* __restrict__ pos, const int* __restrict__ topk,
                          float* __restrict__ x)
{
    int idx = blockIdx.x * 256 + threadIdx.x;
    if (idx >= BATCH * SEQ2 * DMODEL) return;
    int d = idx % DMODEL;
    int r = (idx / DMODEL) % SEQ2;
    int b = idx / (DMODEL * SEQ2);
    float v;
    if (r == 0) v = xe[(size_t)b*SEQ1*DMODEL + d];
    else if (r <= SELN*PLENN) {
        int j = (r - 1) / PLENN, l = (r - 1) % PLENN;
        int pi = topk[b*SELN + j];
        v = prompts[((size_t)pi*PLENN + l)*DMODEL + d] + pos[d];
    } else {
        v = xe[((size_t)b*SEQ1 + (r - SELN*PLENN))*DMODEL + d];
    }
    x[idx] = v;
}

// mean over prompt tokens then head matmul, fused (one block per batch image)
__global__ void feat_head_k(const float* __restrict__ hln,
                            const float* __restrict__ hw, const float* __restrict__ hb,
                            float* __restrict__ feat, float* __restrict__ out)
{
    int b = blockIdx.x;
    int t = threadIdx.x;
    #pragma unroll
    for (int e = 0; e < 3; e++) {
        int d = t + e * 256;
        float s = 0.f;
        #pragma unroll
        for (int r = 1; r <= SELN*PLENN; r++)
            s += hln[((size_t)b*SEQ2 + r)*DMODEL + d];
        feat[(size_t)b*DMODEL + d] = s * (1.f / (SELN*PLENN));
    }
    __syncthreads();
    for (int n = t; n < NCLSN; n += 256) {
        float s = hb[n];
        for (int k = 0; k < DMODEL; k++)
            s += feat[(size_t)b*DMODEL + k] * hw[(size_t)k*NCLSN + n];
        out[b*NCLSN + n] = s;
    }
}

// ---------------- host orchestration ----------------
struct Ptrs {
    float *x, *h, *qkv, *ao, *mlp, *att, *xe, *qcls, *quad, *lognorm, *feat;
    int* topk;
};

static void run_layer(const Ptrs& P, int S, int l,
                      const float* ln1w, const float* ln1b,
                      const float* qkvw, const float* qkvb,
                      const float* projw, const float* projb,
                      const float* ln2w, const float* ln2b,
                      const float* fc1w, const float* fc1b,
                      const float* fc2w, const float* fc2b)
{
    int BS = BATCH * S;
    int mt = (BS + 127) / 128;
    int st = (S + 31) / 32;
    layernorm_k<<<BS, 256>>>(P.x, P.h, ln1w + (size_t)l*DMODEL, ln1b + (size_t)l*DMODEL, DMODEL, DMODEL);
    gemm_k<0><<<dim3(2304/128, mt), 256>>>(P.h, qkvw + (size_t)l*DMODEL*2304, qkvb + (size_t)l*2304,
                                           nullptr, P.qkv, BS, 2304, DMODEL);
    attn_scores_k<<<dim3(st, st, BATCH*NHEAD), 256>>>(P.qkv, P.att, S);
    softmax_k<<<BATCH*NHEAD*S, 256>>>(P.att, S);
    attn_av_k<<<dim3(st, BATCH*NHEAD), 256>>>(P.qkv, P.att, P.ao, S);
    gemm_k<2><<<dim3(DMODEL/128, mt), 256>>>(P.ao, projw + (size_t)l*DMODEL*DMODEL, projb + (size_t)l*DMODEL,
                                             P.x, P.x, BS, DMODEL, DMODEL);
    layernorm_k<<<BS, 256>>>(P.x, P.h, ln2w + (size_t)l*DMODEL, ln2b + (size_t)l*DMODEL, DMODEL, DMODEL);
    gemm_k<1><<<dim3(MLPD/128, mt), 256>>>(P.h, fc1w + (size_t)l*DMODEL*MLPD, fc1b + (size_t)l*MLPD,
                                           nullptr, P.mlp, BS, MLPD, DMODEL);
    gemm_k<2><<<dim3(DMODEL/128, mt), 256>>>(P.mlp, fc2w + (size_t)l*MLPD*DMODEL, fc2b + (size_t)l*DMODEL,
                                             P.x, P.x, BS, DMODEL, MLPD);
}

extern "C" void kernel_launch(void* const* d_in, const int* in_sizes, int n_in,
                              void* d_out, int out_size)
{
    (void)in_sizes; (void)n_in; (void)out_size;
    const float* inputs    = (const float*)d_in[0];
    const float* patch_w   = (const float*)d_in[1];
    const float* patch_b   = (const float*)d_in[2];
    const float* cls_token = (const float*)d_in[3];
    const float* pos_embed = (const float*)d_in[4];
    const float* ln1_w = (const float*)d_in[5];
    const float* ln1_b = (const float*)d_in[6];
    const float* qkv_w = (const float*)d_in[7];
    const float* qkv_b = (const float*)d_in[8];
    const float* proj_w = (const float*)d_in[9];
    const float* proj_b = (const float*)d_in[10];
    const float* ln2_w = (const float*)d_in[11];
    const float* ln2_b = (const float*)d_in[12];
    const float* fc1_w = (const float*)d_in[13];
    const float* fc1_b = (const float*)d_in[14];
    const float* fc2_w = (const float*)d_in[15];
    const float* fc2_b = (const float*)d_in[16];
    const float* norm_w = (const float*)d_in[17];
    const float* norm_b = (const float*)d_in[18];
    const float* head_w = (const float*)d_in[19];
    const float* head_b = (const float*)d_in[20];
    const float* key_pool = (const float*)d_in[21];
    const float* frequency = (const float*)d_in[22];
    const float* prompts = (const float*)d_in[23];
    const float* variance = (const float*)d_in[24];
    const float* inv_variance = (const float*)d_in[25];
    float* out = (float*)d_out;

    Ptrs P;
    { void* p;
      cudaGetSymbolAddress(&p, g_x);    P.x = (float*)p;
      cudaGetSymbolAddress(&p, g_h);    P.h = (float*)p;
      cudaGetSymbolAddress(&p, g_qkv);  P.qkv = (float*)p;
      cudaGetSymbolAddress(&p, g_ao);   P.ao = (float*)p;
      cudaGetSymbolAddress(&p, g_mlp);  P.mlp = (float*)p;
      cudaGetSymbolAddress(&p, g_att);  P.att = (float*)p;
      cudaGetSymbolAddress(&p, g_xe);   P.xe = (float*)p;
      cudaGetSymbolAddress(&p, g_qcls); P.qcls = (float*)p;
      cudaGetSymbolAddress(&p, g_quad); P.quad = (float*)p;
      cudaGetSymbolAddress(&p, g_lognorm); P.lognorm = (float*)p;
      cudaGetSymbolAddress(&p, g_feat); P.feat = (float*)p;
      cudaGetSymbolAddress(&p, g_topk); P.topk = (int*)p;
    }

    // 1. patchify + patch embed + cls/pos
    int np_elems = BATCH * NPATCH_ * DMODEL;
    patchify_k<<<(np_elems + 255)/256, 256>>>(inputs, P.h);
    gemm_k<0><<<dim3(DMODEL/128, (BATCH*NPATCH_ + 127)/128), 256>>>(
        P.h, patch_w, patch_b, nullptr, P.ao, BATCH*NPATCH_, DMODEL, DMODEL);
    int em_elems = BATCH * SEQ1 * DMODEL;
    embed_k<<<(em_elems + 255)/256, 256>>>(P.ao, cls_token, pos_embed, P.xe, P.x);

    // 2. pass 1 (S=197)
    for (int l = 0; l < NLAYER; l++)
        run_layer(P, SEQ1, l, ln1_w, ln1_b, qkv_w, qkv_b, proj_w, proj_b,
                  ln2_w, ln2_b, fc1_w, fc1_b, fc2_w, fc2_b);

    // 3. CLS layernorm + routing
    layernorm_k<<<BATCH, 256>>>(P.x, P.qcls, norm_w, norm_b, (size_t)SEQ1*DMODEL, DMODEL);
    quad_k<<<BATCH*POOLN, 256>>>(P.qcls, key_pool, inv_variance, P.quad);
    lognorm_k<<<POOLN, 256>>>(variance, P.lognorm);
    topk_k<<<1, 32>>>(P.quad, P.lognorm, frequency, P.topk);

    // 4. build prompted sequence (S=222)
    int sx_elems = BATCH * SEQ2 * DMODEL;
    buildsx_k<<<(sx_elems + 255)/256, 256>>>(P.xe, prompts, pos_embed, P.topk, P.x);

    // 5. pass 2 (S=222)
    for (int l = 0; l < NLAYER; l++)
        run_layer(P, SEQ2, l, ln1_w, ln1_b, qkv_w, qkv_b, proj_w, proj_b,
                  ln2_w, ln2_b, fc1_w, fc1_b, fc2_w, fc2_b);

    // 6. final LN, then fused mean-over-prompts + head
    layernorm_k<<<BATCH*SEQ2, 256>>>(P.x, P.h, norm_w, norm_b, DMODEL, DMODEL);
    feat_head_k<<<BATCH, 256>>>(P.h, head_w, head_b, P.feat, out);
}